// round 1
// baseline (speedup 1.0000x reference)
#include <cuda_runtime.h>

#define D_MODEL 1024
#define SEQ     2048
#define BATCH   2
#define NHEAD   16
#define HDIM    64
#define MTOT    (BATCH * SEQ)   // 4096

// Scratch (no allocation allowed): Q, K, V, attention output — each [4096, 1024] fp32
__device__ float g_q[MTOT * D_MODEL];
__device__ float g_k[MTOT * D_MODEL];
__device__ float g_v[MTOT * D_MODEL];
__device__ float g_att[MTOT * D_MODEL];

// ---------------------------------------------------------------------------
// GEMM: C[M,N] = A[M,K] * W[K,N] + bias[N]
// 128x128 tile, BK=8, 256 threads, 8x8 per thread, reg prefetch of next tile.
// ---------------------------------------------------------------------------
__global__ __launch_bounds__(256) void gemm_bias_kernel(
    const float* __restrict__ A, const float* __restrict__ W,
    const float* __restrict__ bias, float* __restrict__ C,
    int M, int N, int K)
{
    __shared__ float As[8][132];   // A transposed: As[k][m], pad 4 kills store conflicts
    __shared__ float Bs[8][128];   // natural: Bs[k][n]

    const int tid = threadIdx.x;
    const int tx  = tid & 15;
    const int ty  = tid >> 4;
    const int m0  = blockIdx.y * 128;
    const int n0  = blockIdx.x * 128;

    // global load assignments
    const int lam = tid >> 1;         // 0..127 : A row within tile
    const int lak = (tid & 1) * 4;    // 0 or 4 : A col within BK
    const int lbr = tid >> 5;         // 0..7   : W row within BK
    const int lbn = (tid & 31) * 4;   // 0..124 : W col within tile

    const float* Ap = A + (size_t)(m0 + lam) * K + lak;
    const float* Bp = W + (size_t)lbr * N + n0 + lbn;

    float4 pa = *(const float4*)Ap;
    float4 pb = *(const float4*)Bp;

    float acc[8][8];
#pragma unroll
    for (int i = 0; i < 8; i++)
#pragma unroll
        for (int j = 0; j < 8; j++) acc[i][j] = 0.f;

    const int NT = K >> 3;
    for (int kt = 0; kt < NT; kt++) {
        // commit prefetched tile to smem
        As[lak + 0][lam] = pa.x;
        As[lak + 1][lam] = pa.y;
        As[lak + 2][lam] = pa.z;
        As[lak + 3][lam] = pa.w;
        *(float4*)&Bs[lbr][lbn] = pb;
        __syncthreads();

        if (kt + 1 < NT) {
            pa = *(const float4*)(Ap + (kt + 1) * 8);
            pb = *(const float4*)(Bp + (size_t)(kt + 1) * 8 * N);
        }

#pragma unroll
        for (int kk = 0; kk < 8; kk++) {
            float4 a0 = *(const float4*)&As[kk][ty * 4];
            float4 a1 = *(const float4*)&As[kk][64 + ty * 4];
            float4 b0 = *(const float4*)&Bs[kk][tx * 4];
            float4 b1 = *(const float4*)&Bs[kk][64 + tx * 4];
            float av[8] = {a0.x, a0.y, a0.z, a0.w, a1.x, a1.y, a1.z, a1.w};
            float bv[8] = {b0.x, b0.y, b0.z, b0.w, b1.x, b1.y, b1.z, b1.w};
#pragma unroll
            for (int i = 0; i < 8; i++)
#pragma unroll
                for (int j = 0; j < 8; j++)
                    acc[i][j] = fmaf(av[i], bv[j], acc[i][j]);
        }
        __syncthreads();
    }

    // epilogue: + bias, vectorized stores
    float4 bv0 = *(const float4*)&bias[n0 + tx * 4];
    float4 bv1 = *(const float4*)&bias[n0 + 64 + tx * 4];
    float bb[8] = {bv0.x, bv0.y, bv0.z, bv0.w, bv1.x, bv1.y, bv1.z, bv1.w};
#pragma unroll
    for (int i = 0; i < 8; i++) {
        int m = m0 + ((i < 4) ? (ty * 4 + i) : (64 + ty * 4 + (i - 4)));
#pragma unroll
        for (int jh = 0; jh < 2; jh++) {
            float4 o;
            o.x = acc[i][jh * 4 + 0] + bb[jh * 4 + 0];
            o.y = acc[i][jh * 4 + 1] + bb[jh * 4 + 1];
            o.z = acc[i][jh * 4 + 2] + bb[jh * 4 + 2];
            o.w = acc[i][jh * 4 + 3] + bb[jh * 4 + 3];
            *(float4*)&C[(size_t)m * N + n0 + jh * 64 + tx * 4] = o;
        }
    }
}

// ---------------------------------------------------------------------------
// Flash attention, fp32, causal. One CTA = (batch, head, 64-query tile).
// BQ = BK = 64. 256 threads as 16x16, 4x4 fragment per thread.
// smem: Qs[d][q] (transposed), KPs = K transposed [d][k] aliased with P [q][k],
//       Vs[k][d] natural. All row strides 68 floats (float4-aligned, low conflict).
// ---------------------------------------------------------------------------
#define ATT_STRIDE 68
#define ATT_SMEM_BYTES (3 * 64 * ATT_STRIDE * 4)

__global__ __launch_bounds__(256) void flash_attn_kernel(
    const float* __restrict__ Qg, const float* __restrict__ Kg,
    const float* __restrict__ Vg, float* __restrict__ Og)
{
    extern __shared__ float sm[];
    float* Qs  = sm;                        // [64][68]  Qs[d*68 + q]
    float* KPs = sm + 64 * ATT_STRIDE;      // [64][68]  Kst[d*68 + k]  then  Ps[q*68 + k]
    float* Vs  = sm + 2 * 64 * ATT_STRIDE;  // [64][68]  Vs[k*68 + d]

    const int tid = threadIdx.x;
    const int tx  = tid & 15;
    const int ty  = tid >> 4;
    const int qt  = (SEQ / 64 - 1) - (int)blockIdx.x;  // biggest tiles first
    const int h   = blockIdx.y;
    const int b   = blockIdx.z;
    const int q0  = qt * 64;
    const size_t base = ((size_t)b * SEQ) * D_MODEL + h * HDIM;

    const int lr = tid >> 2;   // 0..63 row
    const int lp = tid & 3;    // 0..3

    // load Q tile, transposed into smem
    {
        const float* src = Qg + base + (size_t)(q0 + lr) * D_MODEL;
#pragma unroll
        for (int c = 0; c < 4; c++) {
            int d4 = (lp + 4 * c) * 4;
            float4 v = *(const float4*)(src + d4);
            Qs[(d4 + 0) * ATT_STRIDE + lr] = v.x;
            Qs[(d4 + 1) * ATT_STRIDE + lr] = v.y;
            Qs[(d4 + 2) * ATT_STRIDE + lr] = v.z;
            Qs[(d4 + 3) * ATT_STRIDE + lr] = v.w;
        }
    }

    float m_i[4], l_i[4], o[4][4];
#pragma unroll
    for (int i = 0; i < 4; i++) {
        m_i[i] = -1e30f;
        l_i[i] = 0.f;
#pragma unroll
        for (int j = 0; j < 4; j++) o[i][j] = 0.f;
    }

    for (int kt = 0; kt <= qt; kt++) {
        __syncthreads();   // prior O-gemm done (and Q load on first iter)
        const int k0 = kt * 64;
        {
            const float* ksrc = Kg + base + (size_t)(k0 + lr) * D_MODEL;
            const float* vsrc = Vg + base + (size_t)(k0 + lr) * D_MODEL;
#pragma unroll
            for (int c = 0; c < 4; c++) {
                int d4 = (lp + 4 * c) * 4;
                float4 kv = *(const float4*)(ksrc + d4);
                KPs[(d4 + 0) * ATT_STRIDE + lr] = kv.x;
                KPs[(d4 + 1) * ATT_STRIDE + lr] = kv.y;
                KPs[(d4 + 2) * ATT_STRIDE + lr] = kv.z;
                KPs[(d4 + 3) * ATT_STRIDE + lr] = kv.w;
                *(float4*)&Vs[lr * ATT_STRIDE + d4] = *(const float4*)(vsrc + d4);
            }
        }
        __syncthreads();

        // S = Q * K^T (64x64x64)
        float s[4][4];
#pragma unroll
        for (int i = 0; i < 4; i++)
#pragma unroll
            for (int j = 0; j < 4; j++) s[i][j] = 0.f;

#pragma unroll 4
        for (int d = 0; d < 64; d++) {
            float a0 = Qs[d * ATT_STRIDE + 4 * ty + 0];
            float a1 = Qs[d * ATT_STRIDE + 4 * ty + 1];
            float a2 = Qs[d * ATT_STRIDE + 4 * ty + 2];
            float a3 = Qs[d * ATT_STRIDE + 4 * ty + 3];
            float4 bvec = *(const float4*)&KPs[d * ATT_STRIDE + 4 * tx];
            s[0][0] = fmaf(a0, bvec.x, s[0][0]);
            s[0][1] = fmaf(a0, bvec.y, s[0][1]);
            s[0][2] = fmaf(a0, bvec.z, s[0][2]);
            s[0][3] = fmaf(a0, bvec.w, s[0][3]);
            s[1][0] = fmaf(a1, bvec.x, s[1][0]);
            s[1][1] = fmaf(a1, bvec.y, s[1][1]);
            s[1][2] = fmaf(a1, bvec.z, s[1][2]);
            s[1][3] = fmaf(a1, bvec.w, s[1][3]);
            s[2][0] = fmaf(a2, bvec.x, s[2][0]);
            s[2][1] = fmaf(a2, bvec.y, s[2][1]);
            s[2][2] = fmaf(a2, bvec.z, s[2][2]);
            s[2][3] = fmaf(a2, bvec.w, s[2][3]);
            s[3][0] = fmaf(a3, bvec.x, s[3][0]);
            s[3][1] = fmaf(a3, bvec.y, s[3][1]);
            s[3][2] = fmaf(a3, bvec.z, s[3][2]);
            s[3][3] = fmaf(a3, bvec.w, s[3][3]);
        }

        // scale + causal mask
        const float SCALE = 0.125f;   // 1/sqrt(64)
#pragma unroll
        for (int i = 0; i < 4; i++) {
            int qg = q0 + 4 * ty + i;
#pragma unroll
            for (int j = 0; j < 4; j++) {
                int kg = k0 + 4 * tx + j;
                s[i][j] = (kg <= qg) ? s[i][j] * SCALE : -1e30f;
            }
        }

        // online softmax; row spans 16 tx lanes (xor 8,4,2,1 stays in 16-lane group)
#pragma unroll
        for (int i = 0; i < 4; i++) {
            float mx = fmaxf(fmaxf(s[i][0], s[i][1]), fmaxf(s[i][2], s[i][3]));
#pragma unroll
            for (int off = 8; off > 0; off >>= 1)
                mx = fmaxf(mx, __shfl_xor_sync(0xffffffffu, mx, off));
            float mnew = fmaxf(m_i[i], mx);
            float corr = __expf(m_i[i] - mnew);
            m_i[i] = mnew;
            float rs = 0.f;
#pragma unroll
            for (int j = 0; j < 4; j++) {
                s[i][j] = __expf(s[i][j] - mnew);
                rs += s[i][j];
            }
#pragma unroll
            for (int off = 8; off > 0; off >>= 1)
                rs += __shfl_xor_sync(0xffffffffu, rs, off);
            l_i[i] = l_i[i] * corr + rs;
#pragma unroll
            for (int j = 0; j < 4; j++) o[i][j] *= corr;
        }

        __syncthreads();   // everyone done reading Kst before P overwrites it
#pragma unroll
        for (int i = 0; i < 4; i++)
            *(float4*)&KPs[(4 * ty + i) * ATT_STRIDE + 4 * tx] =
                make_float4(s[i][0], s[i][1], s[i][2], s[i][3]);
        __syncthreads();

        // O += P * V (64x64x64)
#pragma unroll 4
        for (int kk = 0; kk < 64; kk++) {
            float a0 = KPs[(4 * ty + 0) * ATT_STRIDE + kk];
            float a1 = KPs[(4 * ty + 1) * ATT_STRIDE + kk];
            float a2 = KPs[(4 * ty + 2) * ATT_STRIDE + kk];
            float a3 = KPs[(4 * ty + 3) * ATT_STRIDE + kk];
            float4 bvec = *(const float4*)&Vs[kk * ATT_STRIDE + 4 * tx];
            o[0][0] = fmaf(a0, bvec.x, o[0][0]);
            o[0][1] = fmaf(a0, bvec.y, o[0][1]);
            o[0][2] = fmaf(a0, bvec.z, o[0][2]);
            o[0][3] = fmaf(a0, bvec.w, o[0][3]);
            o[1][0] = fmaf(a1, bvec.x, o[1][0]);
            o[1][1] = fmaf(a1, bvec.y, o[1][1]);
            o[1][2] = fmaf(a1, bvec.z, o[1][2]);
            o[1][3] = fmaf(a1, bvec.w, o[1][3]);
            o[2][0] = fmaf(a2, bvec.x, o[2][0]);
            o[2][1] = fmaf(a2, bvec.y, o[2][1]);
            o[2][2] = fmaf(a2, bvec.z, o[2][2]);
            o[2][3] = fmaf(a2, bvec.w, o[2][3]);
            o[3][0] = fmaf(a3, bvec.x, o[3][0]);
            o[3][1] = fmaf(a3, bvec.y, o[3][1]);
            o[3][2] = fmaf(a3, bvec.z, o[3][2]);
            o[3][3] = fmaf(a3, bvec.w, o[3][3]);
        }
    }

    // normalize + write (heads re-concatenated layout: [b, s, h*64 + d])
    float* dst = Og + base;
#pragma unroll
    for (int i = 0; i < 4; i++) {
        float inv = 1.f / l_i[i];
        float4 w = make_float4(o[i][0] * inv, o[i][1] * inv,
                               o[i][2] * inv, o[i][3] * inv);
        *(float4*)&dst[(size_t)(q0 + 4 * ty + i) * D_MODEL + 4 * tx] = w;
    }
}

// ---------------------------------------------------------------------------
extern "C" void kernel_launch(void* const* d_in, const int* in_sizes, int n_in,
                              void* d_out, int out_size)
{
    const float* x  = (const float*)d_in[0];
    const float* Wq = (const float*)d_in[1];
    const float* bq = (const float*)d_in[2];
    const float* Wk = (const float*)d_in[3];
    const float* bk = (const float*)d_in[4];
    const float* Wv = (const float*)d_in[5];
    const float* bv = (const float*)d_in[6];
    const float* Wo = (const float*)d_in[7];
    const float* bo = (const float*)d_in[8];
    float* out = (float*)d_out;
    (void)in_sizes; (void)n_in; (void)out_size;

    float *q, *k, *v, *att;
    cudaGetSymbolAddress((void**)&q,   g_q);
    cudaGetSymbolAddress((void**)&k,   g_k);
    cudaGetSymbolAddress((void**)&v,   g_v);
    cudaGetSymbolAddress((void**)&att, g_att);

    cudaFuncSetAttribute(flash_attn_kernel,
                         cudaFuncAttributeMaxDynamicSharedMemorySize,
                         ATT_SMEM_BYTES);

    dim3 gemm_grid(D_MODEL / 128, MTOT / 128);   // (8, 32)

    gemm_bias_kernel<<<gemm_grid, 256>>>(x, Wq, bq, q, MTOT, D_MODEL, D_MODEL);
    gemm_bias_kernel<<<gemm_grid, 256>>>(x, Wk, bk, k, MTOT, D_MODEL, D_MODEL);
    gemm_bias_kernel<<<gemm_grid, 256>>>(x, Wv, bv, v, MTOT, D_MODEL, D_MODEL);

    dim3 att_grid(SEQ / 64, NHEAD, BATCH);       // (32, 16, 2)
    flash_attn_kernel<<<att_grid, 256, ATT_SMEM_BYTES>>>(q, k, v, att);

    gemm_bias_kernel<<<gemm_grid, 256>>>(att, Wo, bo, out, MTOT, D_MODEL, D_MODEL);
}

// round 4
// speedup vs baseline: 1.1849x; 1.1849x over previous
#include <cuda_runtime.h>
#include <cstdint>

#define D_MODEL 1024
#define SEQ     2048
#define BATCH   2
#define NHEAD   16
#define HDIM    64
#define MTOT    (BATCH * SEQ)   // 4096

// Scratch (no allocation allowed): Q, K, V, attention output — each [4096, 1024] fp32
__device__ float g_q[MTOT * D_MODEL];
__device__ float g_k[MTOT * D_MODEL];
__device__ float g_v[MTOT * D_MODEL];
__device__ float g_att[MTOT * D_MODEL];

// ===========================================================================
// tf32 tensor-core GEMM: C[M,N] = A[M,K] * W[K,N] + bias[N]
// CTA tile 128x128, kTile 16, 256 threads = 8 warps (2m x 4n), warp 64x32.
// mma.sync.aligned.m16n8k8.row.col.f32.tf32.tf32.f32
// smem: k-major, row stride 136 floats -> fragment LDS conflict-free.
// ===========================================================================
#define GST 136

__device__ __forceinline__ uint32_t f2tf32(float x) {
    uint32_t r;
    asm("cvt.rna.tf32.f32 %0, %1;" : "=r"(r) : "f"(x));
    return r;
}

__device__ __forceinline__ void mma_tf32(float* d, const uint32_t* a, const uint32_t* b) {
    asm volatile(
        "mma.sync.aligned.m16n8k8.row.col.f32.tf32.tf32.f32 "
        "{%0,%1,%2,%3}, {%4,%5,%6,%7}, {%8,%9}, {%0,%1,%2,%3};"
        : "+f"(d[0]), "+f"(d[1]), "+f"(d[2]), "+f"(d[3])
        : "r"(a[0]), "r"(a[1]), "r"(a[2]), "r"(a[3]), "r"(b[0]), "r"(b[1]));
}

__global__ __launch_bounds__(256) void gemm_tf32_kernel(
    const float* __restrict__ A, const float* __restrict__ W,
    const float* __restrict__ bias, float* __restrict__ C,
    int M, int N, int K)
{
    __shared__ uint32_t As[16 * GST];   // [k][m], tf32 bits
    __shared__ uint32_t Bs[16 * GST];   // [k][n], tf32 bits

    const int tid  = threadIdx.x;
    const int warp = tid >> 5;
    const int lane = tid & 31;
    const int g    = lane >> 2;   // 0..7
    const int t    = lane & 3;    // 0..3
    const int wm   = (warp & 1) * 64;
    const int wn   = (warp >> 1) * 32;
    const int m0   = blockIdx.y * 128;
    const int n0   = blockIdx.x * 128;

    // global load assignments
    const int am = tid & 127;          // A row in tile
    const int ak = (tid >> 7) * 8;     // A k base (0 or 8)
    const int bk = tid >> 4;           // B k row (0..15)
    const int bn = (tid & 15) * 4;     // B n base (0..60), +64 for second half

    const float* Ap = A + (size_t)(m0 + am) * K + ak;
    const float* Bp = W + (size_t)bk * N + n0 + bn;

    float4 pa0 = *(const float4*)(Ap);
    float4 pa1 = *(const float4*)(Ap + 4);
    float4 pb0 = *(const float4*)(Bp);
    float4 pb1 = *(const float4*)(Bp + 64);

    float acc[4][4][4];
#pragma unroll
    for (int i = 0; i < 4; i++)
#pragma unroll
        for (int j = 0; j < 4; j++)
#pragma unroll
            for (int r = 0; r < 4; r++) acc[i][j][r] = 0.f;

    const int NT = K >> 4;   // 64
    for (int kt = 0; kt < NT; kt++) {
        // commit prefetched tile to smem (converted to tf32)
        As[(ak + 0) * GST + am] = f2tf32(pa0.x);
        As[(ak + 1) * GST + am] = f2tf32(pa0.y);
        As[(ak + 2) * GST + am] = f2tf32(pa0.z);
        As[(ak + 3) * GST + am] = f2tf32(pa0.w);
        As[(ak + 4) * GST + am] = f2tf32(pa1.x);
        As[(ak + 5) * GST + am] = f2tf32(pa1.y);
        As[(ak + 6) * GST + am] = f2tf32(pa1.z);
        As[(ak + 7) * GST + am] = f2tf32(pa1.w);
        {
            uint4 u0 = make_uint4(f2tf32(pb0.x), f2tf32(pb0.y), f2tf32(pb0.z), f2tf32(pb0.w));
            uint4 u1 = make_uint4(f2tf32(pb1.x), f2tf32(pb1.y), f2tf32(pb1.z), f2tf32(pb1.w));
            *(uint4*)&Bs[bk * GST + bn]      = u0;
            *(uint4*)&Bs[bk * GST + bn + 64] = u1;
        }
        __syncthreads();

        if (kt + 1 < NT) {
            pa0 = *(const float4*)(Ap + (kt + 1) * 16);
            pa1 = *(const float4*)(Ap + (kt + 1) * 16 + 4);
            pb0 = *(const float4*)(Bp + (size_t)(kt + 1) * 16 * N);
            pb1 = *(const float4*)(Bp + (size_t)(kt + 1) * 16 * N + 64);
        }

#pragma unroll
        for (int k8 = 0; k8 < 16; k8 += 8) {
            const int rt  = (k8 + t) * GST;
            const int rt4 = (k8 + t + 4) * GST;

            uint32_t bf[4][2];
#pragma unroll
            for (int nf = 0; nf < 4; nf++) {
                bf[nf][0] = Bs[rt  + wn + 8 * nf + g];
                bf[nf][1] = Bs[rt4 + wn + 8 * nf + g];
            }
#pragma unroll
            for (int mf = 0; mf < 4; mf++) {
                uint32_t af[4];
                af[0] = As[rt  + wm + 16 * mf + g];
                af[1] = As[rt  + wm + 16 * mf + g + 8];
                af[2] = As[rt4 + wm + 16 * mf + g];
                af[3] = As[rt4 + wm + 16 * mf + g + 8];
#pragma unroll
                for (int nf = 0; nf < 4; nf++)
                    mma_tf32(acc[mf][nf], af, bf[nf]);
            }
        }
        __syncthreads();
    }

    // epilogue: + bias, float2 stores per fragment half
#pragma unroll
    for (int mf = 0; mf < 4; mf++) {
        const int r0 = m0 + wm + 16 * mf + g;
#pragma unroll
        for (int nf = 0; nf < 4; nf++) {
            const int c = n0 + wn + 8 * nf + 2 * t;
            float2 bb = *(const float2*)&bias[c];
            float2 v0 = make_float2(acc[mf][nf][0] + bb.x, acc[mf][nf][1] + bb.y);
            float2 v1 = make_float2(acc[mf][nf][2] + bb.x, acc[mf][nf][3] + bb.y);
            *(float2*)&C[(size_t)r0 * N + c]       = v0;
            *(float2*)&C[(size_t)(r0 + 8) * N + c] = v1;
        }
    }
}

// ---------------------------------------------------------------------------
// Flash attention, fp32, causal. (R2 retile: 128q x 64k, all-LDS.128 inner loops)
// ---------------------------------------------------------------------------
#define QSTR 132
#define KSTR 68
#define VSTR 68
#define PSTR 72
#define ATT_SMEM_FLOATS (64 * QSTR + 64 * KSTR + 64 * VSTR + 128 * PSTR)
#define ATT_SMEM_BYTES  (ATT_SMEM_FLOATS * 4)   // 105472 B -> 2 CTAs/SM

__global__ __launch_bounds__(256) void flash_attn_kernel(
    const float* __restrict__ Qg, const float* __restrict__ Kg,
    const float* __restrict__ Vg, float* __restrict__ Og)
{
    extern __shared__ float sm[];
    float* Qs  = sm;                                     // [64][QSTR]  Qs[d][q]
    float* Kst = sm + 64 * QSTR;                         // [64][KSTR]  Kst[d][k]
    float* Vs  = sm + 64 * QSTR + 64 * KSTR;             // [64][VSTR]  Vs[k][d]
    float* Ps  = sm + 64 * QSTR + 64 * KSTR + 64 * VSTR; // [128][PSTR] Ps[q][k]

    const int tid = threadIdx.x;
    const int tx  = tid & 15;
    const int ty  = tid >> 4;
    const int qt  = (SEQ / 128 - 1) - (int)blockIdx.x;   // biggest tiles first
    const int h   = blockIdx.y;
    const int b   = blockIdx.z;
    const int q0  = qt * 128;
    const size_t base = ((size_t)b * SEQ) * D_MODEL + h * HDIM;

    // load Q tile (128 x 64), transposed into Qs[d][q]
    {
        const int lr = tid >> 1;
        const int lp = tid & 1;
        const float* src = Qg + base + (size_t)(q0 + lr) * D_MODEL + lp * 32;
#pragma unroll
        for (int c = 0; c < 8; c++) {
            int d4 = lp * 32 + c * 4;
            float4 v = *(const float4*)(src + c * 4);
            Qs[(d4 + 0) * QSTR + lr] = v.x;
            Qs[(d4 + 1) * QSTR + lr] = v.y;
            Qs[(d4 + 2) * QSTR + lr] = v.z;
            Qs[(d4 + 3) * QSTR + lr] = v.w;
        }
    }

    float m_i[8], l_i[8], o[8][4];
#pragma unroll
    for (int i = 0; i < 8; i++) {
        m_i[i] = -1e30f;
        l_i[i] = 0.f;
#pragma unroll
        for (int j = 0; j < 4; j++) o[i][j] = 0.f;
    }

    const int kt_max = 2 * qt + 1;
    for (int kt = 0; kt <= kt_max; kt++) {
        __syncthreads();
        const int k0 = kt * 64;
        {
            const int kr = tid >> 2;
            const int kp = tid & 3;
            const float* ksrc = Kg + base + (size_t)(k0 + kr) * D_MODEL + kp * 16;
            const float* vsrc = Vg + base + (size_t)(k0 + kr) * D_MODEL + kp * 16;
#pragma unroll
            for (int c = 0; c < 4; c++) {
                int d4 = kp * 16 + c * 4;
                float4 kv = *(const float4*)(ksrc + c * 4);
                Kst[(d4 + 0) * KSTR + kr] = kv.x;
                Kst[(d4 + 1) * KSTR + kr] = kv.y;
                Kst[(d4 + 2) * KSTR + kr] = kv.z;
                Kst[(d4 + 3) * KSTR + kr] = kv.w;
                *(float4*)&Vs[kr * VSTR + d4] = *(const float4*)(vsrc + c * 4);
            }
        }
        __syncthreads();

        // S = Q * K^T
        float s[8][4];
#pragma unroll
        for (int i = 0; i < 8; i++)
#pragma unroll
            for (int j = 0; j < 4; j++) s[i][j] = 0.f;

#pragma unroll 4
        for (int d = 0; d < 64; d++) {
            float4 a0 = *(const float4*)&Qs[d * QSTR + 8 * ty];
            float4 a1 = *(const float4*)&Qs[d * QSTR + 8 * ty + 4];
            float4 bvec = *(const float4*)&Kst[d * KSTR + 4 * tx];
            float av[8] = {a0.x, a0.y, a0.z, a0.w, a1.x, a1.y, a1.z, a1.w};
#pragma unroll
            for (int i = 0; i < 8; i++) {
                s[i][0] = fmaf(av[i], bvec.x, s[i][0]);
                s[i][1] = fmaf(av[i], bvec.y, s[i][1]);
                s[i][2] = fmaf(av[i], bvec.z, s[i][2]);
                s[i][3] = fmaf(av[i], bvec.w, s[i][3]);
            }
        }

        // scale + causal mask
        const float SCALE = 0.125f;
#pragma unroll
        for (int i = 0; i < 8; i++) {
            int qg = q0 + 8 * ty + i;
#pragma unroll
            for (int j = 0; j < 4; j++) {
                int kg = k0 + 4 * tx + j;
                s[i][j] = (kg <= qg) ? s[i][j] * SCALE : -1e30f;
            }
        }

        // online softmax
#pragma unroll
        for (int i = 0; i < 8; i++) {
            float mx = fmaxf(fmaxf(s[i][0], s[i][1]), fmaxf(s[i][2], s[i][3]));
#pragma unroll
            for (int off = 8; off > 0; off >>= 1)
                mx = fmaxf(mx, __shfl_xor_sync(0xffffffffu, mx, off));
            float mnew = fmaxf(m_i[i], mx);
            float corr = __expf(m_i[i] - mnew);
            m_i[i] = mnew;
            float rs = 0.f;
#pragma unroll
            for (int j = 0; j < 4; j++) {
                s[i][j] = __expf(s[i][j] - mnew);
                rs += s[i][j];
            }
#pragma unroll
            for (int off = 8; off > 0; off >>= 1)
                rs += __shfl_xor_sync(0xffffffffu, rs, off);
            l_i[i] = l_i[i] * corr + rs;
#pragma unroll
            for (int j = 0; j < 4; j++) o[i][j] *= corr;
        }

#pragma unroll
        for (int i = 0; i < 8; i++)
            *(float4*)&Ps[(8 * ty + i) * PSTR + 4 * tx] =
                make_float4(s[i][0], s[i][1], s[i][2], s[i][3]);
        __syncthreads();

        // O += P * V
#pragma unroll 2
        for (int c4 = 0; c4 < 16; c4++) {
            const int kk = c4 * 4;
            float4 b0 = *(const float4*)&Vs[(kk + 0) * VSTR + 4 * tx];
            float4 b1 = *(const float4*)&Vs[(kk + 1) * VSTR + 4 * tx];
            float4 b2 = *(const float4*)&Vs[(kk + 2) * VSTR + 4 * tx];
            float4 b3 = *(const float4*)&Vs[(kk + 3) * VSTR + 4 * tx];
#pragma unroll
            for (int i = 0; i < 8; i++) {
                float4 p = *(const float4*)&Ps[(8 * ty + i) * PSTR + kk];
                o[i][0] = fmaf(p.x, b0.x, o[i][0]);
                o[i][1] = fmaf(p.x, b0.y, o[i][1]);
                o[i][2] = fmaf(p.x, b0.z, o[i][2]);
                o[i][3] = fmaf(p.x, b0.w, o[i][3]);
                o[i][0] = fmaf(p.y, b1.x, o[i][0]);
                o[i][1] = fmaf(p.y, b1.y, o[i][1]);
                o[i][2] = fmaf(p.y, b1.z, o[i][2]);
                o[i][3] = fmaf(p.y, b1.w, o[i][3]);
                o[i][0] = fmaf(p.z, b2.x, o[i][0]);
                o[i][1] = fmaf(p.z, b2.y, o[i][1]);
                o[i][2] = fmaf(p.z, b2.z, o[i][2]);
                o[i][3] = fmaf(p.z, b2.w, o[i][3]);
                o[i][0] = fmaf(p.w, b3.x, o[i][0]);
                o[i][1] = fmaf(p.w, b3.y, o[i][1]);
                o[i][2] = fmaf(p.w, b3.z, o[i][2]);
                o[i][3] = fmaf(p.w, b3.w, o[i][3]);
            }
        }
    }

    // normalize + write
    float* dst = Og + base;
#pragma unroll
    for (int i = 0; i < 8; i++) {
        float inv = 1.f / l_i[i];
        float4 w = make_float4(o[i][0] * inv, o[i][1] * inv,
                               o[i][2] * inv, o[i][3] * inv);
        *(float4*)&dst[(size_t)(q0 + 8 * ty + i) * D_MODEL + 4 * tx] = w;
    }
}

// ---------------------------------------------------------------------------
extern "C" void kernel_launch(void* const* d_in, const int* in_sizes, int n_in,
                              void* d_out, int out_size)
{
    const float* x  = (const float*)d_in[0];
    const float* Wq = (const float*)d_in[1];
    const float* bq = (const float*)d_in[2];
    const float* Wk = (const float*)d_in[3];
    const float* bk = (const float*)d_in[4];
    const float* Wv = (const float*)d_in[5];
    const float* bv = (const float*)d_in[6];
    const float* Wo = (const float*)d_in[7];
    const float* bo = (const float*)d_in[8];
    float* out = (float*)d_out;
    (void)in_sizes; (void)n_in; (void)out_size;

    float *q, *k, *v, *att;
    cudaGetSymbolAddress((void**)&q,   g_q);
    cudaGetSymbolAddress((void**)&k,   g_k);
    cudaGetSymbolAddress((void**)&v,   g_v);
    cudaGetSymbolAddress((void**)&att, g_att);

    cudaFuncSetAttribute(flash_attn_kernel,
                         cudaFuncAttributeMaxDynamicSharedMemorySize,
                         ATT_SMEM_BYTES);

    dim3 gemm_grid(D_MODEL / 128, MTOT / 128);   // (8, 32)

    gemm_tf32_kernel<<<gemm_grid, 256>>>(x, Wq, bq, q, MTOT, D_MODEL, D_MODEL);
    gemm_tf32_kernel<<<gemm_grid, 256>>>(x, Wk, bk, k, MTOT, D_MODEL, D_MODEL);
    gemm_tf32_kernel<<<gemm_grid, 256>>>(x, Wv, bv, v, MTOT, D_MODEL, D_MODEL);

    dim3 att_grid(SEQ / 128, NHEAD, BATCH);      // (16, 16, 2)
    flash_attn_kernel<<<att_grid, 256, ATT_SMEM_BYTES>>>(q, k, v, att);

    gemm_tf32_kernel<<<gemm_grid, 256>>>(att, Wo, bo, out, MTOT, D_MODEL, D_MODEL);
}

// round 6
// speedup vs baseline: 1.6607x; 1.4015x over previous
#include <cuda_runtime.h>
#include <cstdint>

#define D_MODEL 1024
#define SEQ     2048
#define BATCH   2
#define NHEAD   16
#define HDIM    64
#define MTOT    (BATCH * SEQ)   // 4096

// Scratch (no allocation allowed)
__device__ float g_q[MTOT * D_MODEL];
__device__ float g_k[MTOT * D_MODEL];
__device__ float g_v[MTOT * D_MODEL];
__device__ float g_att[MTOT * D_MODEL];

__device__ __forceinline__ uint32_t f2tf32(float x) {
    uint32_t r;
    asm("cvt.rna.tf32.f32 %0, %1;" : "=r"(r) : "f"(x));
    return r;
}

__device__ __forceinline__ void mma_tf32(float* d, const uint32_t* a, const uint32_t* b) {
    asm volatile(
        "mma.sync.aligned.m16n8k8.row.col.f32.tf32.tf32.f32 "
        "{%0,%1,%2,%3}, {%4,%5,%6,%7}, {%8,%9}, {%0,%1,%2,%3};"
        : "+f"(d[0]), "+f"(d[1]), "+f"(d[2]), "+f"(d[3])
        : "r"(a[0]), "r"(a[1]), "r"(a[2]), "r"(a[3]), "r"(b[0]), "r"(b[1]));
}

// ===========================================================================
// tf32 tensor-core GEMM (unchanged from R4 — passing, ~70 TF/s)
// ===========================================================================
#define GST 136

__global__ __launch_bounds__(256) void gemm_tf32_kernel(
    const float* __restrict__ A, const float* __restrict__ W,
    const float* __restrict__ bias, float* __restrict__ C,
    int M, int N, int K)
{
    __shared__ uint32_t As[16 * GST];
    __shared__ uint32_t Bs[16 * GST];

    const int tid  = threadIdx.x;
    const int warp = tid >> 5;
    const int lane = tid & 31;
    const int g    = lane >> 2;
    const int t    = lane & 3;
    const int wm   = (warp & 1) * 64;
    const int wn   = (warp >> 1) * 32;
    const int m0   = blockIdx.y * 128;
    const int n0   = blockIdx.x * 128;

    const int am = tid & 127;
    const int ak = (tid >> 7) * 8;
    const int bk = tid >> 4;
    const int bn = (tid & 15) * 4;

    const float* Ap = A + (size_t)(m0 + am) * K + ak;
    const float* Bp = W + (size_t)bk * N + n0 + bn;

    float4 pa0 = *(const float4*)(Ap);
    float4 pa1 = *(const float4*)(Ap + 4);
    float4 pb0 = *(const float4*)(Bp);
    float4 pb1 = *(const float4*)(Bp + 64);

    float acc[4][4][4];
#pragma unroll
    for (int i = 0; i < 4; i++)
#pragma unroll
        for (int j = 0; j < 4; j++)
#pragma unroll
            for (int r = 0; r < 4; r++) acc[i][j][r] = 0.f;

    const int NT = K >> 4;
    for (int kt = 0; kt < NT; kt++) {
        As[(ak + 0) * GST + am] = f2tf32(pa0.x);
        As[(ak + 1) * GST + am] = f2tf32(pa0.y);
        As[(ak + 2) * GST + am] = f2tf32(pa0.z);
        As[(ak + 3) * GST + am] = f2tf32(pa0.w);
        As[(ak + 4) * GST + am] = f2tf32(pa1.x);
        As[(ak + 5) * GST + am] = f2tf32(pa1.y);
        As[(ak + 6) * GST + am] = f2tf32(pa1.z);
        As[(ak + 7) * GST + am] = f2tf32(pa1.w);
        {
            uint4 u0 = make_uint4(f2tf32(pb0.x), f2tf32(pb0.y), f2tf32(pb0.z), f2tf32(pb0.w));
            uint4 u1 = make_uint4(f2tf32(pb1.x), f2tf32(pb1.y), f2tf32(pb1.z), f2tf32(pb1.w));
            *(uint4*)&Bs[bk * GST + bn]      = u0;
            *(uint4*)&Bs[bk * GST + bn + 64] = u1;
        }
        __syncthreads();

        if (kt + 1 < NT) {
            pa0 = *(const float4*)(Ap + (kt + 1) * 16);
            pa1 = *(const float4*)(Ap + (kt + 1) * 16 + 4);
            pb0 = *(const float4*)(Bp + (size_t)(kt + 1) * 16 * N);
            pb1 = *(const float4*)(Bp + (size_t)(kt + 1) * 16 * N + 64);
        }

#pragma unroll
        for (int k8 = 0; k8 < 16; k8 += 8) {
            const int rt  = (k8 + t) * GST;
            const int rt4 = (k8 + t + 4) * GST;

            uint32_t bf[4][2];
#pragma unroll
            for (int nf = 0; nf < 4; nf++) {
                bf[nf][0] = Bs[rt  + wn + 8 * nf + g];
                bf[nf][1] = Bs[rt4 + wn + 8 * nf + g];
            }
#pragma unroll
            for (int mf = 0; mf < 4; mf++) {
                uint32_t af[4];
                af[0] = As[rt  + wm + 16 * mf + g];
                af[1] = As[rt  + wm + 16 * mf + g + 8];
                af[2] = As[rt4 + wm + 16 * mf + g];
                af[3] = As[rt4 + wm + 16 * mf + g + 8];
#pragma unroll
                for (int nf = 0; nf < 4; nf++)
                    mma_tf32(acc[mf][nf], af, bf[nf]);
            }
        }
        __syncthreads();
    }

#pragma unroll
    for (int mf = 0; mf < 4; mf++) {
        const int r0 = m0 + wm + 16 * mf + g;
#pragma unroll
        for (int nf = 0; nf < 4; nf++) {
            const int c = n0 + wn + 8 * nf + 2 * t;
            float2 bb = *(const float2*)&bias[c];
            float2 v0 = make_float2(acc[mf][nf][0] + bb.x, acc[mf][nf][1] + bb.y);
            float2 v1 = make_float2(acc[mf][nf][2] + bb.x, acc[mf][nf][3] + bb.y);
            *(float2*)&C[(size_t)r0 * N + c]       = v0;
            *(float2*)&C[(size_t)(r0 + 8) * N + c] = v1;
        }
    }
}

// ===========================================================================
// Tensor-core flash attention (tf32, causal).
// CTA = (b, h, 128-q tile); 8 warps; warp owns 16 q rows x full 64 k width.
// S-gemm: Q (persistent tf32 reg frags, scale folded) x K (smem tf32).
// Softmax fp32 in c-layout regs; quad shuffles only.
// O-gemm: P (smem tf32) x (Vh + Vl) split tf32 -> V truncation error killed.
// smem: QsPs region (Qs[d][q] str136, reused as Ps[k][q] str132),
//       Kst[d][k] str72, Vh[k][d] str72, Vl[k][d] str72.  90112 B -> 2 CTAs/SM.
// ===========================================================================
#define AQ_STR 136
#define AK_STR 72
#define AV_STR 72
#define AP_STR 132
#define ATT_SMEM_WORDS (64 * AQ_STR + 3 * 64 * AV_STR)
#define ATT_SMEM_BYTES (ATT_SMEM_WORDS * 4)   // 90112

__global__ __launch_bounds__(256, 2) void flash_attn_tc_kernel(
    const float* __restrict__ Qg, const float* __restrict__ Kg,
    const float* __restrict__ Vg, float* __restrict__ Og)
{
    extern __shared__ uint32_t smu[];
    uint32_t* QsPs = smu;                       // Qs then Ps (aliased)
    uint32_t* Kst  = smu + 64 * AQ_STR;
    uint32_t* Vh   = Kst + 64 * AK_STR;
    uint32_t* Vl   = Vh  + 64 * AV_STR;

    const int tid  = threadIdx.x;
    const int warp = tid >> 5;
    const int lane = tid & 31;
    const int g    = lane >> 2;
    const int t    = lane & 3;
    const int qwb  = warp * 16;                 // warp's local q base

    const int qt = (SEQ / 128 - 1) - (int)blockIdx.x;   // biggest tiles first
    const int h  = blockIdx.y;
    const int b  = blockIdx.z;
    const int q0 = qt * 128;
    const size_t base = ((size_t)b * SEQ) * D_MODEL + h * HDIM;

    // ---- load Q tile (128x64) -> Qs[d][q], tf32, scale 1/8 folded (exact) ----
    {
        const int lr = tid >> 1;
        const int lp = tid & 1;
        const float* src = Qg + base + (size_t)(q0 + lr) * D_MODEL + lp * 32;
#pragma unroll
        for (int c = 0; c < 8; c++) {
            int d4 = lp * 32 + c * 4;
            float4 v = *(const float4*)(src + c * 4);
            QsPs[(d4 + 0) * AQ_STR + lr] = f2tf32(0.125f * v.x);
            QsPs[(d4 + 1) * AQ_STR + lr] = f2tf32(0.125f * v.y);
            QsPs[(d4 + 2) * AQ_STR + lr] = f2tf32(0.125f * v.z);
            QsPs[(d4 + 3) * AQ_STR + lr] = f2tf32(0.125f * v.w);
        }
    }
    __syncthreads();

    // ---- persistent Q a-fragments (16q x 64d per warp = 32 regs) ----
    uint32_t qa[8][4];
#pragma unroll
    for (int s = 0; s < 8; s++) {
        const int r0 = (8 * s + t) * AQ_STR;
        const int r4 = (8 * s + t + 4) * AQ_STR;
        qa[s][0] = QsPs[r0 + qwb + g];
        qa[s][1] = QsPs[r0 + qwb + g + 8];
        qa[s][2] = QsPs[r4 + qwb + g];
        qa[s][3] = QsPs[r4 + qwb + g + 8];
    }

    float oacc[8][4];
#pragma unroll
    for (int nt = 0; nt < 8; nt++)
#pragma unroll
        for (int r = 0; r < 4; r++) oacc[nt][r] = 0.f;
    float m0 = -1e30f, m1 = -1e30f, l0 = 0.f, l1 = 0.f;

    const int kt_max = 2 * qt + 1;
    for (int kt = 0; kt <= kt_max; kt++) {
        __syncthreads();   // prior O-gemm done (also orders Q-frag loads vs first P STS)
        const int k0 = kt * 64;

        // ---- load K (transposed, tf32) and V (split tf32 h+l) tiles ----
        {
            const int kr = tid >> 2;
            const int kp = tid & 3;
            const float* ksrc = Kg + base + (size_t)(k0 + kr) * D_MODEL + kp * 16;
            const float* vsrc = Vg + base + (size_t)(k0 + kr) * D_MODEL + kp * 16;
#pragma unroll
            for (int c = 0; c < 4; c++) {
                const int d4 = kp * 16 + c * 4;
                float4 kv = *(const float4*)(ksrc + c * 4);
                Kst[(d4 + 0) * AK_STR + kr] = f2tf32(kv.x);
                Kst[(d4 + 1) * AK_STR + kr] = f2tf32(kv.y);
                Kst[(d4 + 2) * AK_STR + kr] = f2tf32(kv.z);
                Kst[(d4 + 3) * AK_STR + kr] = f2tf32(kv.w);
                float4 vv = *(const float4*)(vsrc + c * 4);
                uint4 vh, vl;
                vh.x = f2tf32(vv.x); vl.x = f2tf32(vv.x - __uint_as_float(vh.x));
                vh.y = f2tf32(vv.y); vl.y = f2tf32(vv.y - __uint_as_float(vh.y));
                vh.z = f2tf32(vv.z); vl.z = f2tf32(vv.z - __uint_as_float(vh.z));
                vh.w = f2tf32(vv.w); vl.w = f2tf32(vv.w - __uint_as_float(vh.w));
                *(uint4*)&Vh[kr * AV_STR + d4] = vh;
                *(uint4*)&Vl[kr * AV_STR + d4] = vl;
            }
        }
        __syncthreads();

        // ---- S = (Q/8) * K^T : 16q x 64k per warp ----
        float sacc[8][4];
#pragma unroll
        for (int nt = 0; nt < 8; nt++)
#pragma unroll
            for (int r = 0; r < 4; r++) sacc[nt][r] = 0.f;

#pragma unroll
        for (int s = 0; s < 8; s++) {
            const int rt  = (8 * s + t) * AK_STR;
            const int rt4 = (8 * s + t + 4) * AK_STR;
#pragma unroll
            for (int nt = 0; nt < 8; nt++) {
                uint32_t kb[2];
                kb[0] = Kst[rt  + 8 * nt + g];
                kb[1] = Kst[rt4 + 8 * nt + g];
                mma_tf32(sacc[nt], qa[s], kb);
            }
        }

        // ---- causal mask (only tiles that touch the diagonal of this warp) ----
        if (k0 + 63 > q0 + qwb) {
            const int row0 = q0 + qwb + g;
#pragma unroll
            for (int nt = 0; nt < 8; nt++) {
                const int c0 = k0 + 8 * nt + 2 * t;
                if (c0 > row0)     sacc[nt][0] = -1e30f;
                if (c0 + 1 > row0) sacc[nt][1] = -1e30f;
                if (c0 > row0 + 8)     sacc[nt][2] = -1e30f;
                if (c0 + 1 > row0 + 8) sacc[nt][3] = -1e30f;
            }
        }

        // ---- online softmax (rows g and g+8; quad reduce: xor 1, 2) ----
        {
            float mx0 = -1e30f, mx1 = -1e30f;
#pragma unroll
            for (int nt = 0; nt < 8; nt++) {
                mx0 = fmaxf(mx0, fmaxf(sacc[nt][0], sacc[nt][1]));
                mx1 = fmaxf(mx1, fmaxf(sacc[nt][2], sacc[nt][3]));
            }
            mx0 = fmaxf(mx0, __shfl_xor_sync(0xffffffffu, mx0, 1));
            mx0 = fmaxf(mx0, __shfl_xor_sync(0xffffffffu, mx0, 2));
            mx1 = fmaxf(mx1, __shfl_xor_sync(0xffffffffu, mx1, 1));
            mx1 = fmaxf(mx1, __shfl_xor_sync(0xffffffffu, mx1, 2));

            const float nm0 = fmaxf(m0, mx0);
            const float nm1 = fmaxf(m1, mx1);
            const float cr0 = __expf(m0 - nm0);
            const float cr1 = __expf(m1 - nm1);
            m0 = nm0; m1 = nm1;

            float rs0 = 0.f, rs1 = 0.f;
#pragma unroll
            for (int nt = 0; nt < 8; nt++) {
                sacc[nt][0] = __expf(sacc[nt][0] - nm0);
                sacc[nt][1] = __expf(sacc[nt][1] - nm0);
                sacc[nt][2] = __expf(sacc[nt][2] - nm1);
                sacc[nt][3] = __expf(sacc[nt][3] - nm1);
                rs0 += sacc[nt][0] + sacc[nt][1];
                rs1 += sacc[nt][2] + sacc[nt][3];
            }
            rs0 += __shfl_xor_sync(0xffffffffu, rs0, 1);
            rs0 += __shfl_xor_sync(0xffffffffu, rs0, 2);
            rs1 += __shfl_xor_sync(0xffffffffu, rs1, 1);
            rs1 += __shfl_xor_sync(0xffffffffu, rs1, 2);
            l0 = l0 * cr0 + rs0;
            l1 = l1 * cr1 + rs1;
#pragma unroll
            for (int nt = 0; nt < 8; nt++) {
                oacc[nt][0] *= cr0; oacc[nt][1] *= cr0;
                oacc[nt][2] *= cr1; oacc[nt][3] *= cr1;
            }
        }

        // ---- store P as tf32 into Ps[k][q] (aliases dead Qs) ----
#pragma unroll
        for (int nt = 0; nt < 8; nt++) {
            const int kc = 8 * nt + 2 * t;
            QsPs[kc * AP_STR + qwb + g]           = f2tf32(sacc[nt][0]);
            QsPs[(kc + 1) * AP_STR + qwb + g]     = f2tf32(sacc[nt][1]);
            QsPs[kc * AP_STR + qwb + g + 8]       = f2tf32(sacc[nt][2]);
            QsPs[(kc + 1) * AP_STR + qwb + g + 8] = f2tf32(sacc[nt][3]);
        }
        __syncthreads();

        // ---- O += P * (Vh + Vl) : 16q x 64d per warp ----
#pragma unroll
        for (int s = 0; s < 8; s++) {
            const int pr  = (8 * s + t) * AP_STR;
            const int pr4 = (8 * s + t + 4) * AP_STR;
            uint32_t pa[4];
            pa[0] = QsPs[pr  + qwb + g];
            pa[1] = QsPs[pr  + qwb + g + 8];
            pa[2] = QsPs[pr4 + qwb + g];
            pa[3] = QsPs[pr4 + qwb + g + 8];
            const int rt  = (8 * s + t) * AV_STR;
            const int rt4 = (8 * s + t + 4) * AV_STR;
#pragma unroll
            for (int nt = 0; nt < 8; nt++) {
                uint32_t vb[2];
                vb[0] = Vh[rt  + 8 * nt + g];
                vb[1] = Vh[rt4 + 8 * nt + g];
                mma_tf32(oacc[nt], pa, vb);
                vb[0] = Vl[rt  + 8 * nt + g];
                vb[1] = Vl[rt4 + 8 * nt + g];
                mma_tf32(oacc[nt], pa, vb);
            }
        }
    }

    // ---- normalize + write (heads re-concatenated: [b, s, h*64 + d]) ----
    {
        float* dst = Og + base;
        const float inv0 = 1.f / l0;
        const float inv1 = 1.f / l1;
        const size_t r0 = (size_t)(q0 + qwb + g) * D_MODEL;
        const size_t r1 = (size_t)(q0 + qwb + g + 8) * D_MODEL;
#pragma unroll
        for (int nt = 0; nt < 8; nt++) {
            const int col = 8 * nt + 2 * t;
            *(float2*)&dst[r0 + col] = make_float2(oacc[nt][0] * inv0, oacc[nt][1] * inv0);
            *(float2*)&dst[r1 + col] = make_float2(oacc[nt][2] * inv1, oacc[nt][3] * inv1);
        }
    }
}

// ---------------------------------------------------------------------------
extern "C" void kernel_launch(void* const* d_in, const int* in_sizes, int n_in,
                              void* d_out, int out_size)
{
    const float* x  = (const float*)d_in[0];
    const float* Wq = (const float*)d_in[1];
    const float* bq = (const float*)d_in[2];
    const float* Wk = (const float*)d_in[3];
    const float* bk = (const float*)d_in[4];
    const float* Wv = (const float*)d_in[5];
    const float* bv = (const float*)d_in[6];
    const float* Wo = (const float*)d_in[7];
    const float* bo = (const float*)d_in[8];
    float* out = (float*)d_out;
    (void)in_sizes; (void)n_in; (void)out_size;

    float *q, *k, *v, *att;
    cudaGetSymbolAddress((void**)&q,   g_q);
    cudaGetSymbolAddress((void**)&k,   g_k);
    cudaGetSymbolAddress((void**)&v,   g_v);
    cudaGetSymbolAddress((void**)&att, g_att);

    cudaFuncSetAttribute(flash_attn_tc_kernel,
                         cudaFuncAttributeMaxDynamicSharedMemorySize,
                         ATT_SMEM_BYTES);

    dim3 gemm_grid(D_MODEL / 128, MTOT / 128);   // (8, 32)

    gemm_tf32_kernel<<<gemm_grid, 256>>>(x, Wq, bq, q, MTOT, D_MODEL, D_MODEL);
    gemm_tf32_kernel<<<gemm_grid, 256>>>(x, Wk, bk, k, MTOT, D_MODEL, D_MODEL);
    gemm_tf32_kernel<<<gemm_grid, 256>>>(x, Wv, bv, v, MTOT, D_MODEL, D_MODEL);

    dim3 att_grid(SEQ / 128, NHEAD, BATCH);      // (16, 16, 2)
    flash_attn_tc_kernel<<<att_grid, 256, ATT_SMEM_BYTES>>>(q, k, v, att);

    gemm_tf32_kernel<<<gemm_grid, 256>>>(att, Wo, bo, out, MTOT, D_MODEL, D_MODEL);
}